// round 2
// baseline (speedup 1.0000x reference)
#include <cuda_runtime.h>
#include <math.h>

#define T_OBS 8
#define EPSBN 1e-5f

typedef unsigned long long u64;

// ---------------- static device scratch (no runtime allocation) ------------
#define MAXB 131072
__device__ float  g_h[MAXB * 64];
__device__ float  g_c[MAXB * 64];
__device__ float  g_z[MAXB * 16];
__device__ float  g_last[MAXB * 2];
__device__ float  g_W[80 * 256];      // k-major: k<16 = (Wih @ se_W2)^T, k>=16 = Whh^T
__device__ float  g_bias[256];        // bih + bhh + Wih @ se_b2
__device__ double g_enc_stats[5];
__device__ double g_se_stats[5];
__device__ double g_hp_stats[32];
__device__ float  g_enc_fold[48];     // a[16], b[16], c[16]
__device__ float  g_dec_fold[48];
__device__ float  g_hp_scale[16];
__device__ float  g_hp_shift[16];

// ---------------- helpers ---------------------------------------------------
__device__ __forceinline__ float scalar_f(const void* p) {
    // input scalar may be int32 or float32; disambiguate by bit pattern
    int iv = *(const int*)p;
    float fv = __int_as_float(iv);
    if (fv >= 1e-3f && fv <= 1e7f) return fv;
    return (float)iv;
}

__device__ __forceinline__ float fast_sig(float x) {
    float t; asm("ex2.approx.f32 %0, %1;" : "=f"(t) : "f"(-1.4426950408889634f * x));
    float r; asm("rcp.approx.f32 %0, %1;" : "=f"(r) : "f"(1.0f + t));
    return r;
}
__device__ __forceinline__ float fast_tanh(float x) {
    // tanh(x) = 1 - 2/(exp(2x)+1)
    float t; asm("ex2.approx.f32 %0, %1;" : "=f"(t) : "f"(2.8853900817779268f * x));
    float r; asm("rcp.approx.f32 %0, %1;" : "=f"(r) : "f"(1.0f + t));
    return 1.0f - 2.0f * r;
}

__device__ __forceinline__ u64 pack2(float w) {
    u64 r; asm("mov.b64 %0, {%1, %1};" : "=l"(r) : "f"(w)); return r;
}
__device__ __forceinline__ u64 pack22(float a, float b) {
    u64 r; asm("mov.b64 %0, {%1, %2};" : "=l"(r) : "f"(a), "f"(b)); return r;
}
__device__ __forceinline__ void ffma2(u64& d, u64 a, u64 b) {
    asm("fma.rn.f32x2 %0, %1, %2, %0;" : "+l"(d) : "l"(a), "l"(b));
}
__device__ __forceinline__ float2 unpack2(u64 v) {
    float2 r; asm("mov.b64 {%0, %1}, %2;" : "=f"(r.x), "=f"(r.y) : "l"(v)); return r;
}

__device__ __forceinline__ float wred(float v) {
#pragma unroll
    for (int o = 16; o > 0; o >>= 1) v += __shfl_down_sync(0xffffffffu, v, o);
    return v;
}

// ---------------- init: zero h, c, enc stats -------------------------------
__global__ void k_init(int B) {
    size_t n4 = (size_t)B * 64 / 4;
    size_t idx = blockIdx.x * (size_t)blockDim.x + threadIdx.x;
    size_t stride = (size_t)gridDim.x * blockDim.x;
    float4 z4 = make_float4(0.f, 0.f, 0.f, 0.f);
    float4* h4 = (float4*)g_h;
    float4* c4 = (float4*)g_c;
    for (size_t i = idx; i < n4; i += stride) { h4[i] = z4; c4[i] = z4; }
    if (idx < 5) g_enc_stats[idx] = 0.0;
}

// ---------------- prep: fold se_W2/se_b2 into Wih; transpose weights -------
__global__ void k_prep(const float* __restrict__ Wih, const float* __restrict__ Whh,
                       const float* __restrict__ bih, const float* __restrict__ bhh,
                       const float* __restrict__ seW2, const float* __restrict__ seb2) {
    int gc = threadIdx.x;  // 0..255 gate columns
    float wr[64];
#pragma unroll 8
    for (int m = 0; m < 64; m++) wr[m] = Wih[gc * 64 + m];
    float be = bih[gc] + bhh[gc];
#pragma unroll 8
    for (int m = 0; m < 64; m++) be += wr[m] * seb2[m];
    g_bias[gc] = be;
    for (int j = 0; j < 16; j++) {
        float s = 0.f;
#pragma unroll 8
        for (int m = 0; m < 64; m++) s += wr[m] * seW2[m * 16 + j];
        g_W[j * 256 + gc] = s;
    }
#pragma unroll 8
    for (int k = 0; k < 64; k++) g_W[(16 + k) * 256 + gc] = Whh[gc * 64 + k];
}

// ---------------- moments of normalized obs (encode BN) + init last_pos ----
__global__ void k_moments(const float* __restrict__ obs, const void* pxm, const void* pym,
                          int TB, int B) {
    float invx = 1.0f / scalar_f(pxm), invy = 1.0f / scalar_f(pym);
    int idx = blockIdx.x * blockDim.x + threadIdx.x;
    int stride = gridDim.x * blockDim.x;
    float s0 = 0, s1 = 0, s2 = 0, s3 = 0, s4 = 0;
    for (int i = idx; i < TB; i += stride) {
        float x = obs[2 * i] * invx, y = obs[2 * i + 1] * invy;
        s0 += x; s1 += y; s2 += x * x; s3 += y * y; s4 += x * y;
    }
    s0 = wred(s0); s1 = wred(s1); s2 = wred(s2); s3 = wred(s3); s4 = wred(s4);
    if ((threadIdx.x & 31) == 0) {
        atomicAdd(&g_enc_stats[0], (double)s0);
        atomicAdd(&g_enc_stats[1], (double)s1);
        atomicAdd(&g_enc_stats[2], (double)s2);
        atomicAdd(&g_enc_stats[3], (double)s3);
        atomicAdd(&g_enc_stats[4], (double)s4);
    }
    int off = TB - B;  // last frame
    for (int i = idx; i < B; i += stride) {
        g_last[2 * i]     = obs[2 * (off + i)]     * invx;
        g_last[2 * i + 1] = obs[2 * (off + i) + 1] * invy;
    }
}

// ---------------- fold spatial-embedding BN into 2->16 affine --------------
__global__ void k_fold(const float* __restrict__ seW1, const float* __restrict__ seb1,
                       const float* __restrict__ gamma, const float* __restrict__ beta,
                       const void* pxm, const void* pym, int which, float Ninv) {
    const double* st = which ? g_se_stats : g_enc_stats;
    float* fold = which ? g_dec_fold : g_enc_fold;
    double mx = st[0] * Ninv, my = st[1] * Ninv;
    double vxx = st[2] * Ninv - mx * mx;
    double vyy = st[3] * Ninv - my * my;
    double cxy = st[4] * Ninv - mx * my;
    int j = threadIdx.x;
    if (j < 16) {
        float w0 = seW1[2 * j], w1 = seW1[2 * j + 1];
        float mu = (float)(w0 * mx + w1 * my) + seb1[j];
        float var = (float)((double)w0 * w0 * vxx + (double)w1 * w1 * vyy +
                            2.0 * (double)w0 * w1 * cxy);
        float sc = gamma[j] * rsqrtf(var + EPSBN);
        float invx = which ? 1.0f : 1.0f / scalar_f(pxm);
        float invy = which ? 1.0f : 1.0f / scalar_f(pym);
        fold[j]      = w0 * sc * invx;
        fold[16 + j] = w1 * sc * invy;
        fold[32 + j] = (seb1[j] - mu) * sc + beta[j];
    }
    if (j < 32) g_hp_stats[j] = 0.0;  // clear for next hidden-proj reduction
}

// ---------------- LSTM step: feats(2->16,relu) + [feats;h] @ W(80x256) -----
__global__ void __launch_bounds__(256, 2)
k_lstm(const float* __restrict__ obs, int tIdx, int useLast, int B, int nTiles) {
    extern __shared__ float sm[];
    float* Ws = sm;                       // 80*256 floats
    float* bs = sm + 20480;               // 256 floats
    u64*   acts = (u64*)(sm + 20736);     // 16 pairs x 80 k, packed (row0,row1)

    const float* xy = useLast ? g_last : (obs + (size_t)tIdx * B * 2);
    const float* fold = useLast ? g_dec_fold : g_enc_fold;

    int tid = threadIdx.x;
    {   // stage weights + bias into smem
        const float4* src = (const float4*)g_W;
        float4* dst = (float4*)Ws;
        for (int i = tid; i < 20480 / 4; i += 256) dst[i] = src[i];
        bs[tid] = g_bias[tid];
    }
    int fj = tid & 15;
    float fa = fold[fj], fb = fold[16 + fj], fc = fold[32 + fj];
    int s = tid >> 6, j = tid & 63;

    for (int tile = blockIdx.x; tile < nTiles; tile += gridDim.x) {
        int row0 = tile * 32;
        __syncthreads();
        {   // stage 16 relu feats for rows (2p, 2p+1); thread: p = tid>>4, j = fj
            int p = tid >> 4;
            const float* q = xy + (size_t)(row0 + 2 * p) * 2;
            float x0 = q[0], y0 = q[1], x1 = q[2], y1 = q[3];
            float f0 = fmaxf(fa * x0 + fb * y0 + fc, 0.f);
            float f1 = fmaxf(fa * x1 + fb * y1 + fc, 0.f);
            acts[p * 80 + fj] = pack22(f0, f1);
        }
        {   // stage h: thread k = tid&63, pair stride 4
            int k = tid & 63, pp = tid >> 6;
#pragma unroll
            for (int p = pp; p < 16; p += 4) {
                int r = row0 + 2 * p;
                float h0 = g_h[(size_t)r * 64 + k];
                float h1 = g_h[(size_t)(r + 1) * 64 + k];
                acts[p * 80 + 16 + k] = pack22(h0, h1);
            }
        }
        __syncthreads();

        u64 acc[4][4];
#pragma unroll
        for (int p = 0; p < 4; p++)
#pragma unroll
            for (int g = 0; g < 4; g++) acc[p][g] = pack2(bs[g * 64 + j]);

        const u64* ab = acts + s * 4 * 80;
#pragma unroll 4
        for (int k = 0; k < 80; k++) {
            u64 w0 = pack2(Ws[k * 256 + j]);
            u64 w1 = pack2(Ws[k * 256 + 64 + j]);
            u64 w2 = pack2(Ws[k * 256 + 128 + j]);
            u64 w3 = pack2(Ws[k * 256 + 192 + j]);
            u64 a0 = ab[k], a1 = ab[80 + k], a2 = ab[160 + k], a3 = ab[240 + k];
            ffma2(acc[0][0], a0, w0); ffma2(acc[0][1], a0, w1);
            ffma2(acc[0][2], a0, w2); ffma2(acc[0][3], a0, w3);
            ffma2(acc[1][0], a1, w0); ffma2(acc[1][1], a1, w1);
            ffma2(acc[1][2], a1, w2); ffma2(acc[1][3], a1, w3);
            ffma2(acc[2][0], a2, w0); ffma2(acc[2][1], a2, w1);
            ffma2(acc[2][2], a2, w2); ffma2(acc[2][3], a2, w3);
            ffma2(acc[3][0], a3, w0); ffma2(acc[3][1], a3, w1);
            ffma2(acc[3][2], a3, w2); ffma2(acc[3][3], a3, w3);
        }

        // pointwise LSTM update (gate order i,f,g,o)
#pragma unroll
        for (int p = 0; p < 4; p++) {
            int r = row0 + 8 * s + 2 * p;
            float2 iv = unpack2(acc[p][0]);
            float2 fv = unpack2(acc[p][1]);
            float2 gv = unpack2(acc[p][2]);
            float2 ov = unpack2(acc[p][3]);
            size_t i0 = (size_t)r * 64 + j, i1 = i0 + 64;
            float c0 = g_c[i0], c1 = g_c[i1];
            float cn0 = fast_sig(fv.x) * c0 + fast_sig(iv.x) * fast_tanh(gv.x);
            float cn1 = fast_sig(fv.y) * c1 + fast_sig(iv.y) * fast_tanh(gv.y);
            g_c[i0] = cn0; g_c[i1] = cn1;
            g_h[i0] = fast_sig(ov.x) * fast_tanh(cn0);
            g_h[i1] = fast_sig(ov.y) * fast_tanh(cn1);
        }
    }
}

// ---------------- hidden2pos proj: z = h @ hp_W1^T + b1, accumulate stats --
__global__ void k_hp(const float* __restrict__ hpW1, const float* __restrict__ hpb1, int B) {
    __shared__ float Ws[1024];
    for (int i = threadIdx.x; i < 1024; i += 256) Ws[i] = hpW1[i];
    __syncthreads();
    int r0 = (blockIdx.x * 256 + threadIdx.x) * 2;
    float z0[16], z1[16];
#pragma unroll
    for (int jj = 0; jj < 16; jj++) { float b = hpb1[jj]; z0[jj] = b; z1[jj] = b; }
    const float4* ha = (const float4*)(g_h + (size_t)r0 * 64);
    const float4* hb = (const float4*)(g_h + (size_t)(r0 + 1) * 64);
#pragma unroll 4
    for (int kk = 0; kk < 16; kk++) {
        float4 a = ha[kk], b = hb[kk];
#pragma unroll
        for (int jj = 0; jj < 16; jj++) {
            const float* w = &Ws[jj * 64 + 4 * kk];
            z0[jj] += a.x * w[0] + a.y * w[1] + a.z * w[2] + a.w * w[3];
            z1[jj] += b.x * w[0] + b.y * w[1] + b.z * w[2] + b.w * w[3];
        }
    }
    float4* zo = (float4*)(g_z + (size_t)r0 * 16);
    zo[0] = make_float4(z0[0], z0[1], z0[2], z0[3]);
    zo[1] = make_float4(z0[4], z0[5], z0[6], z0[7]);
    zo[2] = make_float4(z0[8], z0[9], z0[10], z0[11]);
    zo[3] = make_float4(z0[12], z0[13], z0[14], z0[15]);
    zo[4] = make_float4(z1[0], z1[1], z1[2], z1[3]);
    zo[5] = make_float4(z1[4], z1[5], z1[6], z1[7]);
    zo[6] = make_float4(z1[8], z1[9], z1[10], z1[11]);
    zo[7] = make_float4(z1[12], z1[13], z1[14], z1[15]);
    float sv[16], qv[16];
#pragma unroll
    for (int jj = 0; jj < 16; jj++) {
        sv[jj] = z0[jj] + z1[jj];
        qv[jj] = z0[jj] * z0[jj] + z1[jj] * z1[jj];
    }
#pragma unroll
    for (int jj = 0; jj < 16; jj++) { sv[jj] = wred(sv[jj]); qv[jj] = wred(qv[jj]); }
    if ((threadIdx.x & 31) == 0) {
#pragma unroll
        for (int jj = 0; jj < 16; jj++) {
            atomicAdd(&g_hp_stats[jj], (double)sv[jj]);
            atomicAdd(&g_hp_stats[16 + jj], (double)qv[jj]);
        }
    }
}

// ---------------- finalize hp BN scale/shift; clear se stats ---------------
__global__ void k_hp_fin(const float* __restrict__ gamma, const float* __restrict__ beta,
                         float Binv) {
    int j = threadIdx.x;
    if (j < 16) {
        double mu = g_hp_stats[j] * Binv;
        double var = g_hp_stats[16 + j] * Binv - mu * mu;
        float sc = gamma[j] * rsqrtf((float)var + EPSBN);
        g_hp_scale[j] = sc;
        g_hp_shift[j] = beta[j] - (float)mu * sc;
    }
    if (j < 5) g_se_stats[j] = 0.0;
}

// ---------------- positions: BN+relu+W2, sigmoid, out, se moments ----------
__global__ void k_pos(const float* __restrict__ hpW2, const float* __restrict__ hpb2,
                      float* __restrict__ out, const void* pxm, const void* pym, int B) {
    int row = blockIdx.x * 256 + threadIdx.x;
    const float4* zr = (const float4*)(g_z + (size_t)row * 16);
    float px = hpb2[0], py = hpb2[1];
#pragma unroll
    for (int q4 = 0; q4 < 4; q4++) {
        float4 v = zr[q4];
        float vv[4] = {v.x, v.y, v.z, v.w};
#pragma unroll
        for (int e = 0; e < 4; e++) {
            int j = q4 * 4 + e;
            float t = fmaxf(vv[e] * g_hp_scale[j] + g_hp_shift[j], 0.f);
            px += t * hpW2[j];
            py += t * hpW2[16 + j];
        }
    }
    float lx = fast_sig(px + g_last[2 * row]);
    float ly = fast_sig(py + g_last[2 * row + 1]);
    g_last[2 * row] = lx;
    g_last[2 * row + 1] = ly;
    out[2 * row]     = lx * scalar_f(pxm);
    out[2 * row + 1] = ly * scalar_f(pym);
    float s0 = wred(lx), s1 = wred(ly);
    float s2 = wred(lx * lx), s3 = wred(ly * ly), s4 = wred(lx * ly);
    if ((threadIdx.x & 31) == 0) {
        atomicAdd(&g_se_stats[0], (double)s0);
        atomicAdd(&g_se_stats[1], (double)s1);
        atomicAdd(&g_se_stats[2], (double)s2);
        atomicAdd(&g_se_stats[3], (double)s3);
        atomicAdd(&g_se_stats[4], (double)s4);
    }
}

// ---------------- launch ----------------------------------------------------
extern "C" void kernel_launch(void* const* d_in, const int* in_sizes, int n_in,
                              void* d_out, int out_size) {
    const float* obs  = (const float*)d_in[0];
    const float* seW1 = (const float*)d_in[1];
    const float* seb1 = (const float*)d_in[2];
    const float* seg  = (const float*)d_in[3];
    const float* seb  = (const float*)d_in[4];
    const float* seW2 = (const float*)d_in[5];
    const float* seb2 = (const float*)d_in[6];
    const float* hpW1 = (const float*)d_in[7];
    const float* hpb1 = (const float*)d_in[8];
    const float* hpg  = (const float*)d_in[9];
    const float* hpb  = (const float*)d_in[10];
    const float* hpW2 = (const float*)d_in[11];
    const float* hpb2 = (const float*)d_in[12];
    const float* Wih  = (const float*)d_in[13];
    const float* Whh  = (const float*)d_in[14];
    const float* bih  = (const float*)d_in[15];
    const float* bhh  = (const float*)d_in[16];
    const void*  pxm  = d_in[17];
    const void*  pym  = d_in[18];

    int B = in_sizes[0] / (T_OBS * 2);
    int TB = T_OBS * B;
    int predLen = out_size / (2 * B);
    float* out = (float*)d_out;

    const int LSTM_SMEM = (20480 + 256) * 4 + 16 * 80 * 8;  // 93184 B
    cudaFuncSetAttribute(k_lstm, cudaFuncAttributeMaxDynamicSharedMemorySize, LSTM_SMEM);

    int nTiles = B / 32;

    k_init<<<1024, 256>>>(B);
    k_prep<<<1, 256>>>(Wih, Whh, bih, bhh, seW2, seb2);
    k_moments<<<512, 256>>>(obs, pxm, pym, TB, B);
    k_fold<<<1, 32>>>(seW1, seb1, seg, seb, pxm, pym, 0, 1.0f / (float)TB);

    for (int t = 0; t < T_OBS; t++)
        k_lstm<<<296, 256, LSTM_SMEM>>>(obs, t, 0, B, nTiles);

    for (int s = 0; s < predLen; s++) {
        k_hp<<<B / 512, 256>>>(hpW1, hpb1, B);
        k_hp_fin<<<1, 32>>>(hpg, hpb, 1.0f / (float)B);
        k_pos<<<B / 256, 256>>>(hpW2, hpb2, out + (size_t)s * B * 2, pxm, pym, B);
        k_fold<<<1, 32>>>(seW1, seb1, seg, seb, pxm, pym, 1, 1.0f / (float)B);
        k_lstm<<<296, 256, LSTM_SMEM>>>(obs, 0, 1, B, nTiles);
    }
}

// round 4
// speedup vs baseline: 1.2940x; 1.2940x over previous
#include <cuda_runtime.h>
#include <cuda_bf16.h>
#include <math.h>

#define T_OBS 8
#define EPSBN 1e-5f

typedef unsigned int u32;
typedef unsigned long long u64;

#define MAXB 131072
#define WSTR 88   // padded k-stride (bf16 elems) for ldmatrix bank spread

// ---------------- static device scratch ------------------------------------
__device__ float  g_h[MAXB * 64];
__device__ float  g_c[MAXB * 64];
__device__ float  g_z[MAXB * 16];
__device__ float  g_last[MAXB * 2];
__device__ __align__(16) __nv_bfloat16 g_Wh[256 * WSTR];
__device__ __align__(16) __nv_bfloat16 g_Wl[256 * WSTR];
__device__ float  g_bias[256];
__device__ double g_enc_stats[5];
__device__ double g_se_stats[5];
__device__ double g_hp_stats[32];

// ---------------- helpers ----------------------------------------------------
__device__ __forceinline__ float scalar_f(const void* p) {
    int iv = *(const int*)p;
    float fv = __int_as_float(iv);
    if (fv >= 1e-3f && fv <= 1e7f) return fv;
    return (float)iv;
}
__device__ __forceinline__ float fast_sig(float x) {
    float t; asm("ex2.approx.f32 %0, %1;" : "=f"(t) : "f"(-1.4426950408889634f * x));
    float r; asm("rcp.approx.f32 %0, %1;" : "=f"(r) : "f"(1.0f + t));
    return r;
}
__device__ __forceinline__ float fast_tanh(float x) {
    float t; asm("ex2.approx.f32 %0, %1;" : "=f"(t) : "f"(2.8853900817779268f * x));
    float r; asm("rcp.approx.f32 %0, %1;" : "=f"(r) : "f"(1.0f + t));
    return 1.0f - 2.0f * r;
}
__device__ __forceinline__ float wred(float v) {
#pragma unroll
    for (int o = 16; o > 0; o >>= 1) v += __shfl_down_sync(0xffffffffu, v, o);
    return v;
}
__device__ __forceinline__ u32 smem_u32(const void* p) {
    u32 a;
    asm("{ .reg .u64 t; cvta.to.shared.u64 t, %1; cvt.u32.u64 %0, t; }" : "=r"(a) : "l"(p));
    return a;
}
__device__ __forceinline__ void ldsm4(u32* r, u32 addr) {
    asm volatile("ldmatrix.sync.aligned.m8n8.x4.shared.b16 {%0,%1,%2,%3}, [%4];"
        : "=r"(r[0]), "=r"(r[1]), "=r"(r[2]), "=r"(r[3]) : "r"(addr));
}
__device__ __forceinline__ void ldsm2(u32* r, u32 addr) {
    asm volatile("ldmatrix.sync.aligned.m8n8.x2.shared.b16 {%0,%1}, [%2];"
        : "=r"(r[0]), "=r"(r[1]) : "r"(addr));
}
__device__ __forceinline__ void mma16816(float* d, const u32* a, const u32* b) {
    asm volatile(
        "mma.sync.aligned.m16n8k16.row.col.f32.bf16.bf16.f32 "
        "{%0,%1,%2,%3},{%4,%5,%6,%7},{%8,%9},{%0,%1,%2,%3};"
        : "+f"(d[0]), "+f"(d[1]), "+f"(d[2]), "+f"(d[3])
        : "r"(a[0]), "r"(a[1]), "r"(a[2]), "r"(a[3]), "r"(b[0]), "r"(b[1]));
}

// ---------------- init: zero h, c, enc stats --------------------------------
__global__ void k_init(int B) {
    size_t n4 = (size_t)B * 64 / 4;
    size_t idx = blockIdx.x * (size_t)blockDim.x + threadIdx.x;
    size_t stride = (size_t)gridDim.x * blockDim.x;
    float4 z4 = make_float4(0.f, 0.f, 0.f, 0.f);
    float4* h4 = (float4*)g_h;
    float4* c4 = (float4*)g_c;
    for (size_t i = idx; i < n4; i += stride) { h4[i] = z4; c4[i] = z4; }
    if (idx < 5) g_enc_stats[idx] = 0.0;
}

// ---------------- prep: fold se_W2/se_b2 into Wih; bf16-split weights --------
__global__ void k_prep(const float* __restrict__ Wih, const float* __restrict__ Whh,
                       const float* __restrict__ bih, const float* __restrict__ bhh,
                       const float* __restrict__ seW2, const float* __restrict__ seb2) {
    int gc = threadIdx.x;  // 0..255: gate column (row of B^T weight matrix)
    float wr[64];
#pragma unroll 8
    for (int m = 0; m < 64; m++) wr[m] = Wih[gc * 64 + m];
    float be = bih[gc] + bhh[gc];
#pragma unroll 8
    for (int m = 0; m < 64; m++) be += wr[m] * seb2[m];
    g_bias[gc] = be;
    for (int k = 0; k < WSTR; k++) {
        float w = 0.f;
        if (k < 16) {
#pragma unroll 8
            for (int m = 0; m < 64; m++) w += wr[m] * seW2[m * 16 + k];
        } else if (k < 80) {
            w = Whh[gc * 64 + (k - 16)];
        }
        __nv_bfloat16 hi = __float2bfloat16(w);
        __nv_bfloat16 lo = __float2bfloat16(w - __bfloat162float(hi));
        g_Wh[gc * WSTR + k] = hi;
        g_Wl[gc * WSTR + k] = lo;
    }
}

// ---------------- moments of normalized obs + init last_pos -----------------
__global__ void k_moments(const float* __restrict__ obs, const void* pxm, const void* pym,
                          int TB, int B) {
    float invx = 1.0f / scalar_f(pxm), invy = 1.0f / scalar_f(pym);
    int idx = blockIdx.x * blockDim.x + threadIdx.x;
    int stride = gridDim.x * blockDim.x;
    float s0 = 0, s1 = 0, s2 = 0, s3 = 0, s4 = 0;
    for (int i = idx; i < TB; i += stride) {
        float x = obs[2 * i] * invx, y = obs[2 * i + 1] * invy;
        s0 += x; s1 += y; s2 += x * x; s3 += y * y; s4 += x * y;
    }
    s0 = wred(s0); s1 = wred(s1); s2 = wred(s2); s3 = wred(s3); s4 = wred(s4);
    if ((threadIdx.x & 31) == 0) {
        atomicAdd(&g_enc_stats[0], (double)s0);
        atomicAdd(&g_enc_stats[1], (double)s1);
        atomicAdd(&g_enc_stats[2], (double)s2);
        atomicAdd(&g_enc_stats[3], (double)s3);
        atomicAdd(&g_enc_stats[4], (double)s4);
    }
    int off = TB - B;
    for (int i = idx; i < B; i += stride) {
        g_last[2 * i]     = obs[2 * (off + i)]     * invx;
        g_last[2 * i + 1] = obs[2 * (off + i) + 1] * invy;
    }
}

// ---------------- LSTM step via mma.sync bf16 (3-term split) ----------------
// smem byte offsets:
#define O_WH   0                    // 256*176 = 45056
#define O_WL   45056                // 45056
#define O_AH   90112                // 64*176 = 11264
#define O_AL   101376               // 11264
#define O_BIAS 112640               // 1024
#define O_FOLD 113664               // 192
#define LSTM_SMEM 113920

__global__ void __launch_bounds__(256, 1)
k_lstm(const float* __restrict__ obs, int tIdx, int useLast, int B, int nTiles,
       const float* __restrict__ seW1, const float* __restrict__ seb1,
       const float* __restrict__ seg, const float* __restrict__ seb,
       const void* pxm, const void* pym, float Ninv) {
    extern __shared__ char sm[];
    float* bs = (float*)(sm + O_BIAS);
    float* fold = (float*)(sm + O_FOLD);
    u32 smb = smem_u32(sm);
    int tid = threadIdx.x, wid = tid >> 5, lane = tid & 31;

    {   // stage hi/lo weights into smem
        const float4* s1 = (const float4*)g_Wh;
        const float4* s2 = (const float4*)g_Wl;
        float4* d1 = (float4*)(sm + O_WH);
        float4* d2 = (float4*)(sm + O_WL);
        for (int i = tid; i < 2816; i += 256) { d1[i] = s1[i]; d2[i] = s2[i]; }
    }
    bs[tid] = g_bias[tid];
    if (blockIdx.x == 0 && tid < 32) g_hp_stats[tid] = 0.0;
    if (tid < 16) {   // analytic BN fold for the spatial embedding
        const double* st = useLast ? g_se_stats : g_enc_stats;
        double mx = st[0] * Ninv, my = st[1] * Ninv;
        double vxx = st[2] * Ninv - mx * mx;
        double vyy = st[3] * Ninv - my * my;
        double cxy = st[4] * Ninv - mx * my;
        float w0 = seW1[2 * tid], w1 = seW1[2 * tid + 1];
        float mu = (float)(w0 * mx + w1 * my) + seb1[tid];
        float var = (float)((double)w0 * w0 * vxx + (double)w1 * w1 * vyy +
                            2.0 * (double)w0 * w1 * cxy);
        float sc = seg[tid] * rsqrtf(var + EPSBN);
        float ix = useLast ? 1.f : 1.f / scalar_f(pxm);
        float iy = useLast ? 1.f : 1.f / scalar_f(pym);
        fold[tid]      = w0 * sc * ix;
        fold[16 + tid] = w1 * sc * iy;
        fold[32 + tid] = (seb1[tid] - mu) * sc + seb[tid];
    }

    const float* xy = useLast ? g_last : (obs + (size_t)tIdx * B * 2);
    int arow = tid & 63, q = tid >> 6;       // staging role
    int wm = wid >> 2, wq = wid & 3;          // warp tile role

    for (int tile = blockIdx.x; tile < nTiles; tile += gridDim.x) {
        int row0 = tile * 64;
        __syncthreads();   // weights/fold on iter0; A-consumption done on later iters

        // ----- stage A (feats + h) as bf16 hi/lo -----
        {
            int r = row0 + arow;
            const float* hrow = g_h + (size_t)r * 64;
            float v[20];
            if (q == 0) {
                float x = xy[2 * (size_t)r], y = xy[2 * (size_t)r + 1];
#pragma unroll
                for (int j = 0; j < 16; j++)
                    v[j] = fmaxf(fold[j] * x + fold[16 + j] * y + fold[32 + j], 0.f);
#pragma unroll
                for (int m = 0; m < 4; m++) v[16 + m] = hrow[m];
            } else {
                int base = q * 20 - 16;
#pragma unroll
                for (int m = 0; m < 20; m++) v[m] = hrow[base + m];
            }
            int kb = q * 20;
#pragma unroll
            for (int p = 0; p < 10; p++) {
                float a0 = v[2 * p], a1 = v[2 * p + 1];
                __nv_bfloat16 h0 = __float2bfloat16(a0);
                __nv_bfloat16 h1 = __float2bfloat16(a1);
                __nv_bfloat16 l0 = __float2bfloat16(a0 - __bfloat162float(h0));
                __nv_bfloat16 l1 = __float2bfloat16(a1 - __bfloat162float(h1));
                u32 hp = ((u32)__bfloat16_as_ushort(h1) << 16) | __bfloat16_as_ushort(h0);
                u32 lp = ((u32)__bfloat16_as_ushort(l1) << 16) | __bfloat16_as_ushort(l0);
                int off = arow * (WSTR * 2) + (kb + 2 * p) * 2;
                *(u32*)(sm + O_AH + off) = hp;
                *(u32*)(sm + O_AL + off) = lp;
            }
        }
        __syncthreads();

        // ----- MMA: acc = Ah*Bh + Al*Bh + Ah*Bl, K=80 -----
        float acc[2][4][2][4];
#pragma unroll
        for (int mt = 0; mt < 2; mt++)
#pragma unroll
            for (int g = 0; g < 4; g++)
#pragma unroll
                for (int t = 0; t < 2; t++)
#pragma unroll
                    for (int e = 0; e < 4; e++) acc[mt][g][t][e] = 0.f;

        u32 aRowOff = (u32)((wm * 32 + (lane & 15)) * (WSTR * 2));
        u32 aColSel = (u32)(((lane >> 4) & 1) * 16);          // +8 bf16
        u32 bRowOff = (u32)((lane & 7) * (WSTR * 2));
        u32 bColSel = (u32)(((lane >> 3) & 1) * 16);

#pragma unroll
        for (int kt = 0; kt < 5; kt++) {
            u32 kOff = (u32)(kt * 32);   // 16 bf16 = 32 B
            u32 ah0[4], ah1[4], al0[4], al1[4];
            u32 aAddr = smb + O_AH + aRowOff + kOff + aColSel;
            ldsm4(ah0, aAddr);
            ldsm4(ah1, aAddr + 16 * (WSTR * 2));
            u32 aAddrL = smb + O_AL + aRowOff + kOff + aColSel;
            ldsm4(al0, aAddrL);
            ldsm4(al1, aAddrL + 16 * (WSTR * 2));
#pragma unroll
            for (int g = 0; g < 4; g++) {
#pragma unroll
                for (int t = 0; t < 2; t++) {
                    int nt = g * 8 + wq * 2 + t;
                    u32 bBase = (u32)(nt * 8 * (WSTR * 2)) + bRowOff + kOff + bColSel;
                    u32 bh[2], bl[2];
                    ldsm2(bh, smb + O_WH + bBase);
                    ldsm2(bl, smb + O_WL + bBase);
                    mma16816(acc[0][g][t], ah0, bh);
                    mma16816(acc[1][g][t], ah1, bh);
                    mma16816(acc[0][g][t], al0, bh);
                    mma16816(acc[1][g][t], al1, bh);
                    mma16816(acc[0][g][t], ah0, bl);
                    mma16816(acc[1][g][t], ah1, bl);
                }
            }
        }

        // ----- epilogue: bias + pointwise LSTM update -----
#pragma unroll
        for (int mt = 0; mt < 2; mt++) {
#pragma unroll
            for (int t = 0; t < 2; t++) {
                int j0 = (wq * 2 + t) * 8 + (lane & 3) * 2;
#pragma unroll
                for (int rr = 0; rr < 2; rr++) {
                    int r = row0 + wm * 32 + mt * 16 + rr * 8 + (lane >> 2);
                    float2 c2 = *(float2*)(g_c + (size_t)r * 64 + j0);
                    float cn[2], hn[2];
#pragma unroll
                    for (int cc = 0; cc < 2; cc++) {
                        int e = rr * 2 + cc;
                        float iv = acc[mt][0][t][e] + bs[j0 + cc];
                        float fv = acc[mt][1][t][e] + bs[64 + j0 + cc];
                        float gv = acc[mt][2][t][e] + bs[128 + j0 + cc];
                        float ov = acc[mt][3][t][e] + bs[192 + j0 + cc];
                        float cold = cc ? c2.y : c2.x;
                        float cnew = fast_sig(fv) * cold + fast_sig(iv) * fast_tanh(gv);
                        cn[cc] = cnew;
                        hn[cc] = fast_sig(ov) * fast_tanh(cnew);
                    }
                    *(float2*)(g_c + (size_t)r * 64 + j0) = make_float2(cn[0], cn[1]);
                    *(float2*)(g_h + (size_t)r * 64 + j0) = make_float2(hn[0], hn[1]);
                }
            }
        }
    }
}

// ---------------- hidden2pos proj + stats (also zeroes se stats) ------------
__global__ void k_hp(const float* __restrict__ hpW1, const float* __restrict__ hpb1, int B) {
    __shared__ float Ws[1024];
    for (int i = threadIdx.x; i < 1024; i += 256) Ws[i] = hpW1[i];
    if (blockIdx.x == 0 && threadIdx.x < 5) g_se_stats[threadIdx.x] = 0.0;
    __syncthreads();
    int r0 = (blockIdx.x * 256 + threadIdx.x) * 2;
    float z0[16], z1[16];
#pragma unroll
    for (int jj = 0; jj < 16; jj++) { float b = hpb1[jj]; z0[jj] = b; z1[jj] = b; }
    const float4* ha = (const float4*)(g_h + (size_t)r0 * 64);
    const float4* hb = (const float4*)(g_h + (size_t)(r0 + 1) * 64);
#pragma unroll 4
    for (int kk = 0; kk < 16; kk++) {
        float4 a = ha[kk], b = hb[kk];
#pragma unroll
        for (int jj = 0; jj < 16; jj++) {
            const float* w = &Ws[jj * 64 + 4 * kk];
            z0[jj] += a.x * w[0] + a.y * w[1] + a.z * w[2] + a.w * w[3];
            z1[jj] += b.x * w[0] + b.y * w[1] + b.z * w[2] + b.w * w[3];
        }
    }
    float4* zo = (float4*)(g_z + (size_t)r0 * 16);
    zo[0] = make_float4(z0[0], z0[1], z0[2], z0[3]);
    zo[1] = make_float4(z0[4], z0[5], z0[6], z0[7]);
    zo[2] = make_float4(z0[8], z0[9], z0[10], z0[11]);
    zo[3] = make_float4(z0[12], z0[13], z0[14], z0[15]);
    zo[4] = make_float4(z1[0], z1[1], z1[2], z1[3]);
    zo[5] = make_float4(z1[4], z1[5], z1[6], z1[7]);
    zo[6] = make_float4(z1[8], z1[9], z1[10], z1[11]);
    zo[7] = make_float4(z1[12], z1[13], z1[14], z1[15]);
    float sv[16], qv[16];
#pragma unroll
    for (int jj = 0; jj < 16; jj++) {
        sv[jj] = z0[jj] + z1[jj];
        qv[jj] = z0[jj] * z0[jj] + z1[jj] * z1[jj];
    }
#pragma unroll
    for (int jj = 0; jj < 16; jj++) { sv[jj] = wred(sv[jj]); qv[jj] = wred(qv[jj]); }
    if ((threadIdx.x & 31) == 0) {
#pragma unroll
        for (int jj = 0; jj < 16; jj++) {
            atomicAdd(&g_hp_stats[jj], (double)sv[jj]);
            atomicAdd(&g_hp_stats[16 + jj], (double)qv[jj]);
        }
    }
}

// ---------------- positions: BN(inline)+relu+W2, sigmoid, out, se moments ---
__global__ void k_pos(const float* __restrict__ hpW2, const float* __restrict__ hpb2,
                      const float* __restrict__ gamma, const float* __restrict__ beta,
                      float* __restrict__ out, const void* pxm, const void* pym,
                      float Binv, int B) {
    __shared__ float sc[16], sh[16];
    if (threadIdx.x < 16) {
        int j = threadIdx.x;
        double mu = g_hp_stats[j] * Binv;
        double var = g_hp_stats[16 + j] * Binv - mu * mu;
        float s = gamma[j] * rsqrtf((float)var + EPSBN);
        sc[j] = s;
        sh[j] = beta[j] - (float)mu * s;
    }
    __syncthreads();
    int row = blockIdx.x * 256 + threadIdx.x;
    const float4* zr = (const float4*)(g_z + (size_t)row * 16);
    float px = hpb2[0], py = hpb2[1];
#pragma unroll
    for (int q4 = 0; q4 < 4; q4++) {
        float4 v = zr[q4];
        float vv[4] = {v.x, v.y, v.z, v.w};
#pragma unroll
        for (int e = 0; e < 4; e++) {
            int j = q4 * 4 + e;
            float t = fmaxf(vv[e] * sc[j] + sh[j], 0.f);
            px += t * hpW2[j];
            py += t * hpW2[16 + j];
        }
    }
    float lx = fast_sig(px + g_last[2 * row]);
    float ly = fast_sig(py + g_last[2 * row + 1]);
    g_last[2 * row] = lx;
    g_last[2 * row + 1] = ly;
    out[2 * row]     = lx * scalar_f(pxm);
    out[2 * row + 1] = ly * scalar_f(pym);
    float s0 = wred(lx), s1 = wred(ly);
    float s2 = wred(lx * lx), s3 = wred(ly * ly), s4 = wred(lx * ly);
    if ((threadIdx.x & 31) == 0) {
        atomicAdd(&g_se_stats[0], (double)s0);
        atomicAdd(&g_se_stats[1], (double)s1);
        atomicAdd(&g_se_stats[2], (double)s2);
        atomicAdd(&g_se_stats[3], (double)s3);
        atomicAdd(&g_se_stats[4], (double)s4);
    }
}

// ---------------- launch ------------------------------------------------------
extern "C" void kernel_launch(void* const* d_in, const int* in_sizes, int n_in,
                              void* d_out, int out_size) {
    const float* obs  = (const float*)d_in[0];
    const float* seW1 = (const float*)d_in[1];
    const float* seb1 = (const float*)d_in[2];
    const float* seg  = (const float*)d_in[3];
    const float* seb  = (const float*)d_in[4];
    const float* seW2 = (const float*)d_in[5];
    const float* seb2 = (const float*)d_in[6];
    const float* hpW1 = (const float*)d_in[7];
    const float* hpb1 = (const float*)d_in[8];
    const float* hpg  = (const float*)d_in[9];
    const float* hpb  = (const float*)d_in[10];
    const float* hpW2 = (const float*)d_in[11];
    const float* hpb2 = (const float*)d_in[12];
    const float* Wih  = (const float*)d_in[13];
    const float* Whh  = (const float*)d_in[14];
    const float* bih  = (const float*)d_in[15];
    const float* bhh  = (const float*)d_in[16];
    const void*  pxm  = d_in[17];
    const void*  pym  = d_in[18];

    int B = in_sizes[0] / (T_OBS * 2);
    int TB = T_OBS * B;
    int predLen = out_size / (2 * B);
    float* out = (float*)d_out;
    int nTiles = B / 64;

    cudaFuncSetAttribute(k_lstm, cudaFuncAttributeMaxDynamicSharedMemorySize, LSTM_SMEM);

    k_init<<<1024, 256>>>(B);
    k_prep<<<1, 256>>>(Wih, Whh, bih, bhh, seW2, seb2);
    k_moments<<<512, 256>>>(obs, pxm, pym, TB, B);

    for (int t = 0; t < T_OBS; t++)
        k_lstm<<<148, 256, LSTM_SMEM>>>(obs, t, 0, B, nTiles,
                                        seW1, seb1, seg, seb, pxm, pym, 1.0f / (float)TB);

    for (int s = 0; s < predLen; s++) {
        k_hp<<<B / 512, 256>>>(hpW1, hpb1, B);
        k_pos<<<B / 256, 256>>>(hpW2, hpb2, hpg, hpb, out + (size_t)s * B * 2,
                                pxm, pym, 1.0f / (float)B, B);
        if (s + 1 < predLen)
            k_lstm<<<148, 256, LSTM_SMEM>>>(obs, 0, 1, B, nTiles,
                                            seW1, seb1, seg, seb, pxm, pym, 1.0f / (float)B);
    }
}

// round 5
// speedup vs baseline: 1.8240x; 1.4096x over previous
#include <cuda_runtime.h>
#include <cuda_bf16.h>
#include <math.h>

#define T_OBS 8
#define EPSBN 1e-5f

typedef unsigned int u32;
typedef unsigned long long u64;

#define MAXB 131072
#define WSTR 88   // padded k-stride (bf16 elems): 176B rows -> conflict-free ldmatrix

// ---------------- static device scratch ------------------------------------
__device__ float  g_h[MAXB * 64];
__device__ float  g_c[MAXB * 64];
__device__ float  g_z[MAXB * 16];
__device__ float  g_last[MAXB * 2];
__device__ __align__(16) __nv_bfloat16 g_Wh[256 * WSTR];
__device__ __align__(16) __nv_bfloat16 g_Wl[256 * WSTR];
__device__ float  g_bias[256];
__device__ double g_enc_stats[5];
__device__ double g_se_stats[5];
__device__ double g_hp_stats[32];

// ---------------- helpers ----------------------------------------------------
__device__ __forceinline__ float scalar_f(const void* p) {
    int iv = *(const int*)p;
    float fv = __int_as_float(iv);
    if (fv >= 1e-3f && fv <= 1e7f) return fv;
    return (float)iv;
}
__device__ __forceinline__ float fast_sig(float x) {
    float t; asm("ex2.approx.f32 %0, %1;" : "=f"(t) : "f"(-1.4426950408889634f * x));
    float r; asm("rcp.approx.f32 %0, %1;" : "=f"(r) : "f"(1.0f + t));
    return r;
}
__device__ __forceinline__ float fast_tanh(float x) {
    float t; asm("ex2.approx.f32 %0, %1;" : "=f"(t) : "f"(2.8853900817779268f * x));
    float r; asm("rcp.approx.f32 %0, %1;" : "=f"(r) : "f"(1.0f + t));
    return 1.0f - 2.0f * r;
}
__device__ __forceinline__ float wred(float v) {
#pragma unroll
    for (int o = 16; o > 0; o >>= 1) v += __shfl_down_sync(0xffffffffu, v, o);
    return v;
}
__device__ __forceinline__ u32 smem_u32(const void* p) {
    u32 a;
    asm("{ .reg .u64 t; cvta.to.shared.u64 t, %1; cvt.u32.u64 %0, t; }" : "=r"(a) : "l"(p));
    return a;
}
__device__ __forceinline__ void ldsm4(u32* r, u32 addr) {
    asm volatile("ldmatrix.sync.aligned.m8n8.x4.shared.b16 {%0,%1,%2,%3}, [%4];"
        : "=r"(r[0]), "=r"(r[1]), "=r"(r[2]), "=r"(r[3]) : "r"(addr));
}
__device__ __forceinline__ void mma16816(float* d, const u32* a, const u32* b) {
    asm volatile(
        "mma.sync.aligned.m16n8k16.row.col.f32.bf16.bf16.f32 "
        "{%0,%1,%2,%3},{%4,%5,%6,%7},{%8,%9},{%0,%1,%2,%3};"
        : "+f"(d[0]), "+f"(d[1]), "+f"(d[2]), "+f"(d[3])
        : "r"(a[0]), "r"(a[1]), "r"(a[2]), "r"(a[3]), "r"(b[0]), "r"(b[1]));
}

// ---------------- prep: fold se_W2/se_b2 into Wih; bf16-split weights --------
__global__ void k_prep(const float* __restrict__ Wih, const float* __restrict__ Whh,
                       const float* __restrict__ bih, const float* __restrict__ bhh,
                       const float* __restrict__ seW2, const float* __restrict__ seb2) {
    int gc = threadIdx.x;  // 0..255: gate column
    if (gc < 5) g_enc_stats[gc] = 0.0;
    float wr[64];
#pragma unroll 8
    for (int m = 0; m < 64; m++) wr[m] = Wih[gc * 64 + m];
    float be = bih[gc] + bhh[gc];
#pragma unroll 8
    for (int m = 0; m < 64; m++) be += wr[m] * seb2[m];
    g_bias[gc] = be;
    for (int k = 0; k < WSTR; k++) {
        float w = 0.f;
        if (k < 16) {
#pragma unroll 8
            for (int m = 0; m < 64; m++) w += wr[m] * seW2[m * 16 + k];
        } else if (k < 80) {
            w = Whh[gc * 64 + (k - 16)];
        }
        __nv_bfloat16 hi = __float2bfloat16(w);
        __nv_bfloat16 lo = __float2bfloat16(w - __bfloat162float(hi));
        g_Wh[gc * WSTR + k] = hi;
        g_Wl[gc * WSTR + k] = lo;
    }
}

// ---------------- moments of normalized obs + init last_pos -----------------
__global__ void k_moments(const float* __restrict__ obs, const void* pxm, const void* pym,
                          int TB, int B) {
    __shared__ float red[8][5];
    float invx = 1.0f / scalar_f(pxm), invy = 1.0f / scalar_f(pym);
    int idx = blockIdx.x * blockDim.x + threadIdx.x;
    int stride = gridDim.x * blockDim.x;
    float s[5] = {0, 0, 0, 0, 0};
    for (int i = idx; i < TB; i += stride) {
        float x = obs[2 * i] * invx, y = obs[2 * i + 1] * invy;
        s[0] += x; s[1] += y; s[2] += x * x; s[3] += y * y; s[4] += x * y;
    }
    int wid = threadIdx.x >> 5, lane = threadIdx.x & 31;
#pragma unroll
    for (int k = 0; k < 5; k++) s[k] = wred(s[k]);
    if (lane == 0) {
#pragma unroll
        for (int k = 0; k < 5; k++) red[wid][k] = s[k];
    }
    __syncthreads();
    if (wid == 0 && lane < 5) {
        float t = 0.f;
#pragma unroll
        for (int w = 0; w < 8; w++) t += red[w][lane];
        atomicAdd(&g_enc_stats[lane], (double)t);
    }
    int off = TB - B;
    for (int i = idx; i < B; i += stride) {
        g_last[2 * i]     = obs[2 * (off + i)]     * invx;
        g_last[2 * i + 1] = obs[2 * (off + i) + 1] * invy;
    }
}

// ---------------- LSTM step via mma.sync bf16 (3-term split) ----------------
// smem byte offsets:
#define O_WH   0                    // 256*176 = 45056
#define O_WL   45056                // 45056
#define O_AH   90112                // 64*176 = 11264
#define O_AL   101376               // 11264
#define O_BIAS 112640               // 1024
#define O_FOLD 113664               // 192
#define LSTM_SMEM 113920

// mode: 0 = first encode step (h=c=0, K=16), 1 = encode, 2 = decode
__global__ void __launch_bounds__(512, 1)
k_lstm(const float* __restrict__ obs, int tIdx, int mode, int B, int nTiles,
       const float* __restrict__ seW1, const float* __restrict__ seb1,
       const float* __restrict__ seg, const float* __restrict__ seb,
       const void* pxm, const void* pym, float Ninv) {
    extern __shared__ char sm[];
    float* bs = (float*)(sm + O_BIAS);
    float* fold = (float*)(sm + O_FOLD);
    u32 smb = smem_u32(sm);
    int tid = threadIdx.x, wid = tid >> 5, lane = tid & 31;
    int first = (mode == 0), useLast = (mode == 2);

    {   // stage hi/lo weights into smem
        const float4* s1 = (const float4*)g_Wh;
        const float4* s2 = (const float4*)g_Wl;
        float4* d1 = (float4*)(sm + O_WH);
        float4* d2 = (float4*)(sm + O_WL);
        for (int i = tid; i < 2816; i += 512) { d1[i] = s1[i]; d2[i] = s2[i]; }
    }
    if (tid < 256) bs[tid] = g_bias[tid];
    if (blockIdx.x == 0 && tid < 32) g_hp_stats[tid] = 0.0;
    if (tid < 16) {   // analytic BN fold for the spatial embedding
        const double* st = useLast ? g_se_stats : g_enc_stats;
        double mx = st[0] * Ninv, my = st[1] * Ninv;
        double vxx = st[2] * Ninv - mx * mx;
        double vyy = st[3] * Ninv - my * my;
        double cxy = st[4] * Ninv - mx * my;
        float w0 = seW1[2 * tid], w1 = seW1[2 * tid + 1];
        float mu = (float)(w0 * mx + w1 * my) + seb1[tid];
        float var = (float)((double)w0 * w0 * vxx + (double)w1 * w1 * vyy +
                            2.0 * (double)w0 * w1 * cxy);
        float sc = seg[tid] * rsqrtf(var + EPSBN);
        float ix = useLast ? 1.f : 1.f / scalar_f(pxm);
        float iy = useLast ? 1.f : 1.f / scalar_f(pym);
        fold[tid]      = w0 * sc * ix;
        fold[16 + tid] = w1 * sc * iy;
        fold[32 + tid] = (seb1[tid] - mu) * sc + seb[tid];
    }
    __syncthreads();

    const float* xy = useLast ? g_last : (obs + (size_t)tIdx * B * 2);
    int arow = tid & 63, q = tid >> 6;         // staging role: 10 k's each
    int wm = wid & 1, wn = wid >> 1;           // warp tile: m32 x (n8 per gate)

    // ----- hoist Bh fragments to registers (loop-invariant weights) -----
    u32 bh[5][4][2];
    {
        u32 nrow = (u32)(wn * 8 + (lane & 7));
        u32 gsel = (u32)(((lane >> 4) & 1) * 64);   // matrix 2/3 -> second gate of pair
        u32 ksel = (u32)(((lane >> 3) & 1) * 16);
#pragma unroll
        for (int kt = 0; kt < 5; kt++) {
#pragma unroll
            for (int p = 0; p < 2; p++) {
                u32 r4[4];
                u32 addr = smb + O_WH +
                    ((u32)(p * 2) * 64 + gsel + nrow) * (WSTR * 2) + ksel + (u32)(kt * 32);
                ldsm4(r4, addr);
                bh[kt][2 * p][0] = r4[0]; bh[kt][2 * p][1] = r4[1];
                bh[kt][2 * p + 1][0] = r4[2]; bh[kt][2 * p + 1][1] = r4[3];
            }
        }
    }
    // bias for this thread's 8 columns (4 gates x 2 cols)
    int j0 = wn * 8 + (lane & 3) * 2;
    float bj[4][2];
#pragma unroll
    for (int g = 0; g < 4; g++) { bj[g][0] = bs[g * 64 + j0]; bj[g][1] = bs[g * 64 + j0 + 1]; }

    u32 aRowOff = (u32)((wm * 32 + (lane & 15)) * (WSTR * 2));
    u32 aColSel = (u32)(((lane >> 4) & 1) * 16);
    u32 bRow = (u32)(wn * 8 + (lane & 7));
    u32 bGsel = (u32)(((lane >> 4) & 1) * 64);
    u32 bKsel = (u32)(((lane >> 3) & 1) * 16);
    int nkt = first ? 1 : 5;

    for (int tile = blockIdx.x; tile < nTiles; tile += gridDim.x) {
        int row0 = tile * 64;

        // ----- stage A (feats + h) as bf16 hi/lo -----
        {
            int r = row0 + arow;
            const float* hrow = g_h + (size_t)r * 64;
            int kb = q * 10;
            float v[10];
            if (q == 0) {
                float x = xy[2 * (size_t)r], y = xy[2 * (size_t)r + 1];
#pragma unroll
                for (int m = 0; m < 10; m++)
                    v[m] = fmaxf(fold[m] * x + fold[16 + m] * y + fold[32 + m], 0.f);
            } else if (q == 1) {
                float x = xy[2 * (size_t)r], y = xy[2 * (size_t)r + 1];
#pragma unroll
                for (int m = 0; m < 6; m++) {
                    int j = 10 + m;
                    v[m] = fmaxf(fold[j] * x + fold[16 + j] * y + fold[32 + j], 0.f);
                }
#pragma unroll
                for (int m = 6; m < 10; m++) v[m] = first ? 0.f : hrow[kb + m - 16];
            } else {
                if (!first) {
#pragma unroll
                    for (int m = 0; m < 10; m++) v[m] = hrow[kb + m - 16];
                } else {
#pragma unroll
                    for (int m = 0; m < 10; m++) v[m] = 0.f;
                }
            }
#pragma unroll
            for (int p = 0; p < 5; p++) {
                float a0 = v[2 * p], a1 = v[2 * p + 1];
                __nv_bfloat16 h0 = __float2bfloat16(a0);
                __nv_bfloat16 h1 = __float2bfloat16(a1);
                __nv_bfloat16 l0 = __float2bfloat16(a0 - __bfloat162float(h0));
                __nv_bfloat16 l1 = __float2bfloat16(a1 - __bfloat162float(h1));
                u32 hp = ((u32)__bfloat16_as_ushort(h1) << 16) | __bfloat16_as_ushort(h0);
                u32 lp = ((u32)__bfloat16_as_ushort(l1) << 16) | __bfloat16_as_ushort(l0);
                int off = arow * (WSTR * 2) + (kb + 2 * p) * 2;
                *(u32*)(sm + O_AH + off) = hp;
                *(u32*)(sm + O_AL + off) = lp;
            }
        }
        __syncthreads();

        // ----- MMA: acc = Ah*Bh + Al*Bh + Ah*Bl -----
        float acc[2][4][4];
#pragma unroll
        for (int mt = 0; mt < 2; mt++)
#pragma unroll
            for (int g = 0; g < 4; g++)
#pragma unroll
                for (int e = 0; e < 4; e++) acc[mt][g][e] = 0.f;

#pragma unroll
        for (int kt = 0; kt < 5; kt++) {
            if (kt >= nkt) break;
            u32 kOff = (u32)(kt * 32);
            u32 ah0[4], ah1[4], al0[4], al1[4];
            u32 aAddr = smb + O_AH + aRowOff + aColSel + kOff;
            ldsm4(ah0, aAddr);
            ldsm4(ah1, aAddr + 16 * (WSTR * 2));
            u32 aAddrL = smb + O_AL + aRowOff + aColSel + kOff;
            ldsm4(al0, aAddrL);
            ldsm4(al1, aAddrL + 16 * (WSTR * 2));
            u32 bl[4][2];
#pragma unroll
            for (int p = 0; p < 2; p++) {
                u32 r4[4];
                u32 addr = smb + O_WL +
                    ((u32)(p * 2) * 64 + bGsel + bRow) * (WSTR * 2) + bKsel + kOff;
                ldsm4(r4, addr);
                bl[2 * p][0] = r4[0]; bl[2 * p][1] = r4[1];
                bl[2 * p + 1][0] = r4[2]; bl[2 * p + 1][1] = r4[3];
            }
#pragma unroll
            for (int g = 0; g < 4; g++) {
                mma16816(acc[0][g], ah0, bh[kt][g]);
                mma16816(acc[1][g], ah1, bh[kt][g]);
                mma16816(acc[0][g], al0, bh[kt][g]);
                mma16816(acc[1][g], al1, bh[kt][g]);
                mma16816(acc[0][g], ah0, bl[g]);
                mma16816(acc[1][g], ah1, bl[g]);
            }
        }

        // ----- epilogue: bias + pointwise LSTM update -----
#pragma unroll
        for (int mt = 0; mt < 2; mt++) {
#pragma unroll
            for (int rr = 0; rr < 2; rr++) {
                int r = row0 + wm * 32 + mt * 16 + rr * 8 + (lane >> 2);
                float2 c2 = first ? make_float2(0.f, 0.f)
                                  : *(float2*)(g_c + (size_t)r * 64 + j0);
                float cn[2], hn[2];
#pragma unroll
                for (int cc = 0; cc < 2; cc++) {
                    int e = rr * 2 + cc;
                    float iv = acc[mt][0][e] + bj[0][cc];
                    float fv = acc[mt][1][e] + bj[1][cc];
                    float gv = acc[mt][2][e] + bj[2][cc];
                    float ov = acc[mt][3][e] + bj[3][cc];
                    float cold = cc ? c2.y : c2.x;
                    float cnew = fast_sig(fv) * cold + fast_sig(iv) * fast_tanh(gv);
                    cn[cc] = cnew;
                    hn[cc] = fast_sig(ov) * fast_tanh(cnew);
                }
                *(float2*)(g_c + (size_t)r * 64 + j0) = make_float2(cn[0], cn[1]);
                *(float2*)(g_h + (size_t)r * 64 + j0) = make_float2(hn[0], hn[1]);
            }
        }
        __syncthreads();   // protect A buffer before next staging
    }
}

// ---------------- hidden2pos proj + stats (also zeroes se stats) ------------
__global__ void k_hp(const float* __restrict__ hpW1, const float* __restrict__ hpb1, int B) {
    __shared__ float Ws[1024];
    __shared__ float red[8][32];
    for (int i = threadIdx.x; i < 1024; i += 256) Ws[i] = hpW1[i];
    if (blockIdx.x == 0 && threadIdx.x < 5) g_se_stats[threadIdx.x] = 0.0;
    __syncthreads();
    int r0 = (blockIdx.x * 256 + threadIdx.x) * 2;
    float z0[16], z1[16];
#pragma unroll
    for (int jj = 0; jj < 16; jj++) { float b = hpb1[jj]; z0[jj] = b; z1[jj] = b; }
    const float4* ha = (const float4*)(g_h + (size_t)r0 * 64);
    const float4* hb = (const float4*)(g_h + (size_t)(r0 + 1) * 64);
#pragma unroll 4
    for (int kk = 0; kk < 16; kk++) {
        float4 a = ha[kk], b = hb[kk];
#pragma unroll
        for (int jj = 0; jj < 16; jj++) {
            const float* w = &Ws[jj * 64 + 4 * kk];
            z0[jj] += a.x * w[0] + a.y * w[1] + a.z * w[2] + a.w * w[3];
            z1[jj] += b.x * w[0] + b.y * w[1] + b.z * w[2] + b.w * w[3];
        }
    }
    float4* zo = (float4*)(g_z + (size_t)r0 * 16);
    zo[0] = make_float4(z0[0], z0[1], z0[2], z0[3]);
    zo[1] = make_float4(z0[4], z0[5], z0[6], z0[7]);
    zo[2] = make_float4(z0[8], z0[9], z0[10], z0[11]);
    zo[3] = make_float4(z0[12], z0[13], z0[14], z0[15]);
    zo[4] = make_float4(z1[0], z1[1], z1[2], z1[3]);
    zo[5] = make_float4(z1[4], z1[5], z1[6], z1[7]);
    zo[6] = make_float4(z1[8], z1[9], z1[10], z1[11]);
    zo[7] = make_float4(z1[12], z1[13], z1[14], z1[15]);
    float sv[16], qv[16];
#pragma unroll
    for (int jj = 0; jj < 16; jj++) {
        sv[jj] = z0[jj] + z1[jj];
        qv[jj] = z0[jj] * z0[jj] + z1[jj] * z1[jj];
    }
    int wid = threadIdx.x >> 5, lane = threadIdx.x & 31;
#pragma unroll
    for (int jj = 0; jj < 16; jj++) { sv[jj] = wred(sv[jj]); qv[jj] = wred(qv[jj]); }
    if (lane == 0) {
#pragma unroll
        for (int jj = 0; jj < 16; jj++) { red[wid][jj] = sv[jj]; red[wid][16 + jj] = qv[jj]; }
    }
    __syncthreads();
    if (wid == 0) {
        float t = 0.f;
#pragma unroll
        for (int w = 0; w < 8; w++) t += red[w][lane];
        atomicAdd(&g_hp_stats[lane], (double)t);
    }
}

// ---------------- positions: BN(inline)+relu+W2, sigmoid, out, se moments ---
__global__ void k_pos(const float* __restrict__ hpW2, const float* __restrict__ hpb2,
                      const float* __restrict__ gamma, const float* __restrict__ beta,
                      float* __restrict__ out, const void* pxm, const void* pym,
                      float Binv, int B) {
    __shared__ float sc[16], sh[16];
    __shared__ float red[8][5];
    if (threadIdx.x < 16) {
        int j = threadIdx.x;
        double mu = g_hp_stats[j] * Binv;
        double var = g_hp_stats[16 + j] * Binv - mu * mu;
        float s = gamma[j] * rsqrtf((float)var + EPSBN);
        sc[j] = s;
        sh[j] = beta[j] - (float)mu * s;
    }
    __syncthreads();
    int row = blockIdx.x * 256 + threadIdx.x;
    const float4* zr = (const float4*)(g_z + (size_t)row * 16);
    float px = hpb2[0], py = hpb2[1];
#pragma unroll
    for (int q4 = 0; q4 < 4; q4++) {
        float4 v = zr[q4];
        float vv[4] = {v.x, v.y, v.z, v.w};
#pragma unroll
        for (int e = 0; e < 4; e++) {
            int j = q4 * 4 + e;
            float t = fmaxf(vv[e] * sc[j] + sh[j], 0.f);
            px += t * hpW2[j];
            py += t * hpW2[16 + j];
        }
    }
    float lx = fast_sig(px + g_last[2 * row]);
    float ly = fast_sig(py + g_last[2 * row + 1]);
    g_last[2 * row] = lx;
    g_last[2 * row + 1] = ly;
    out[2 * row]     = lx * scalar_f(pxm);
    out[2 * row + 1] = ly * scalar_f(pym);
    float s[5] = {lx, ly, lx * lx, ly * ly, lx * ly};
    int wid = threadIdx.x >> 5, lane = threadIdx.x & 31;
#pragma unroll
    for (int k = 0; k < 5; k++) s[k] = wred(s[k]);
    if (lane == 0) {
#pragma unroll
        for (int k = 0; k < 5; k++) red[wid][k] = s[k];
    }
    __syncthreads();
    if (wid == 0 && lane < 5) {
        float t = 0.f;
#pragma unroll
        for (int w = 0; w < 8; w++) t += red[w][lane];
        atomicAdd(&g_se_stats[lane], (double)t);
    }
}

// ---------------- launch ------------------------------------------------------
extern "C" void kernel_launch(void* const* d_in, const int* in_sizes, int n_in,
                              void* d_out, int out_size) {
    const float* obs  = (const float*)d_in[0];
    const float* seW1 = (const float*)d_in[1];
    const float* seb1 = (const float*)d_in[2];
    const float* seg  = (const float*)d_in[3];
    const float* seb  = (const float*)d_in[4];
    const float* seW2 = (const float*)d_in[5];
    const float* seb2 = (const float*)d_in[6];
    const float* hpW1 = (const float*)d_in[7];
    const float* hpb1 = (const float*)d_in[8];
    const float* hpg  = (const float*)d_in[9];
    const float* hpb  = (const float*)d_in[10];
    const float* hpW2 = (const float*)d_in[11];
    const float* hpb2 = (const float*)d_in[12];
    const float* Wih  = (const float*)d_in[13];
    const float* Whh  = (const float*)d_in[14];
    const float* bih  = (const float*)d_in[15];
    const float* bhh  = (const float*)d_in[16];
    const void*  pxm  = d_in[17];
    const void*  pym  = d_in[18];

    int B = in_sizes[0] / (T_OBS * 2);
    int TB = T_OBS * B;
    int predLen = out_size / (2 * B);
    float* out = (float*)d_out;
    int nTiles = B / 64;

    cudaFuncSetAttribute(k_lstm, cudaFuncAttributeMaxDynamicSharedMemorySize, LSTM_SMEM);

    k_prep<<<1, 256>>>(Wih, Whh, bih, bhh, seW2, seb2);
    k_moments<<<512, 256>>>(obs, pxm, pym, TB, B);

    for (int t = 0; t < T_OBS; t++)
        k_lstm<<<148, 512, LSTM_SMEM>>>(obs, t, (t == 0) ? 0 : 1, B, nTiles,
                                        seW1, seb1, seg, seb, pxm, pym, 1.0f / (float)TB);

    for (int s = 0; s < predLen; s++) {
        k_hp<<<B / 512, 256>>>(hpW1, hpb1, B);
        k_pos<<<B / 256, 256>>>(hpW2, hpb2, hpg, hpb, out + (size_t)s * B * 2,
                                pxm, pym, 1.0f / (float)B, B);
        if (s + 1 < predLen)
            k_lstm<<<148, 512, LSTM_SMEM>>>(obs, 0, 2, B, nTiles,
                                            seW1, seb1, seg, seb, pxm, pym, 1.0f / (float)B);
    }
}

// round 6
// speedup vs baseline: 2.5492x; 1.3975x over previous
#include <cuda_runtime.h>
#include <cuda_bf16.h>
#include <math.h>

#define T_OBS 8
#define EPSBN 1e-5f

typedef unsigned int u32;
typedef unsigned long long u64;

#define MAXB 131072
#define WSTR 88   // padded k-stride (bf16): 176B rows, conflict-free ldmatrix

// ---------------- static device scratch ------------------------------------
__device__ float  g_h[MAXB * 64];
__device__ float  g_c[MAXB * 64];
__device__ float  g_z[MAXB * 16];
__device__ float  g_last[MAXB * 2];
__device__ __align__(16) __nv_bfloat16 g_Wh[256 * WSTR];
__device__ __align__(16) __nv_bfloat16 g_Wl[256 * WSTR];
__device__ float  g_bias[256];
__device__ double g_enc_stats[5];
__device__ double g_se_stats[5];
__device__ double g_hp_stats[32];

// ---------------- helpers ----------------------------------------------------
__device__ __forceinline__ float scalar_f(const void* p) {
    int iv = *(const int*)p;
    float fv = __int_as_float(iv);
    if (fv >= 1e-3f && fv <= 1e7f) return fv;
    return (float)iv;
}
__device__ __forceinline__ float fast_sig(float x) {
    float t; asm("ex2.approx.f32 %0, %1;" : "=f"(t) : "f"(-1.4426950408889634f * x));
    float r; asm("rcp.approx.f32 %0, %1;" : "=f"(r) : "f"(1.0f + t));
    return r;
}
__device__ __forceinline__ float fast_tanh(float x) {
    float t; asm("ex2.approx.f32 %0, %1;" : "=f"(t) : "f"(2.8853900817779268f * x));
    float r; asm("rcp.approx.f32 %0, %1;" : "=f"(r) : "f"(1.0f + t));
    return 1.0f - 2.0f * r;
}
__device__ __forceinline__ float wred(float v) {
#pragma unroll
    for (int o = 16; o > 0; o >>= 1) v += __shfl_down_sync(0xffffffffu, v, o);
    return v;
}
__device__ __forceinline__ u32 smem_u32(const void* p) {
    u32 a;
    asm("{ .reg .u64 t; cvta.to.shared.u64 t, %1; cvt.u32.u64 %0, t; }" : "=r"(a) : "l"(p));
    return a;
}
__device__ __forceinline__ void ldsm4(u32* r, u32 addr) {
    asm volatile("ldmatrix.sync.aligned.m8n8.x4.shared.b16 {%0,%1,%2,%3}, [%4];"
        : "=r"(r[0]), "=r"(r[1]), "=r"(r[2]), "=r"(r[3]) : "r"(addr));
}
__device__ __forceinline__ void mma16816(float* d, const u32* a, const u32* b) {
    asm volatile(
        "mma.sync.aligned.m16n8k16.row.col.f32.bf16.bf16.f32 "
        "{%0,%1,%2,%3},{%4,%5,%6,%7},{%8,%9},{%0,%1,%2,%3};"
        : "+f"(d[0]), "+f"(d[1]), "+f"(d[2]), "+f"(d[3])
        : "r"(a[0]), "r"(a[1]), "r"(a[2]), "r"(a[3]), "r"(b[0]), "r"(b[1]));
}
__device__ __forceinline__ u32 pack_bf16_hi(float a0, float a1) {
    __nv_bfloat16 h0 = __float2bfloat16(a0), h1 = __float2bfloat16(a1);
    return ((u32)__bfloat16_as_ushort(h1) << 16) | __bfloat16_as_ushort(h0);
}
__device__ __forceinline__ u32 pack_bf16_lo(float a0, float a1) {
    __nv_bfloat16 h0 = __float2bfloat16(a0), h1 = __float2bfloat16(a1);
    __nv_bfloat16 l0 = __float2bfloat16(a0 - __bfloat162float(h0));
    __nv_bfloat16 l1 = __float2bfloat16(a1 - __bfloat162float(h1));
    return ((u32)__bfloat16_as_ushort(l1) << 16) | __bfloat16_as_ushort(l0);
}

// ---------------- prep: fold se_W2/se_b2 into Wih; bf16-split weights --------
__global__ void k_prep(const float* __restrict__ Wih, const float* __restrict__ Whh,
                       const float* __restrict__ bih, const float* __restrict__ bhh,
                       const float* __restrict__ seW2, const float* __restrict__ seb2) {
    int gc = threadIdx.x;
    if (gc < 5) g_enc_stats[gc] = 0.0;
    float wr[64];
#pragma unroll 8
    for (int m = 0; m < 64; m++) wr[m] = Wih[gc * 64 + m];
    float be = bih[gc] + bhh[gc];
#pragma unroll 8
    for (int m = 0; m < 64; m++) be += wr[m] * seb2[m];
    g_bias[gc] = be;
    for (int k = 0; k < WSTR; k++) {
        float w = 0.f;
        if (k < 16) {
#pragma unroll 8
            for (int m = 0; m < 64; m++) w += wr[m] * seW2[m * 16 + k];
        } else if (k < 80) {
            w = Whh[gc * 64 + (k - 16)];
        }
        __nv_bfloat16 hi = __float2bfloat16(w);
        __nv_bfloat16 lo = __float2bfloat16(w - __bfloat162float(hi));
        g_Wh[gc * WSTR + k] = hi;
        g_Wl[gc * WSTR + k] = lo;
    }
}

// ---------------- moments of normalized obs + init last_pos -----------------
__global__ void k_moments(const float* __restrict__ obs, const void* pxm, const void* pym,
                          int TB, int B) {
    __shared__ float red[8][5];
    float invx = 1.0f / scalar_f(pxm), invy = 1.0f / scalar_f(pym);
    int idx = blockIdx.x * blockDim.x + threadIdx.x;
    int stride = gridDim.x * blockDim.x;
    float s[5] = {0, 0, 0, 0, 0};
    for (int i = idx; i < TB; i += stride) {
        float x = obs[2 * i] * invx, y = obs[2 * i + 1] * invy;
        s[0] += x; s[1] += y; s[2] += x * x; s[3] += y * y; s[4] += x * y;
    }
    int wid = threadIdx.x >> 5, lane = threadIdx.x & 31;
#pragma unroll
    for (int k = 0; k < 5; k++) s[k] = wred(s[k]);
    if (lane == 0) {
#pragma unroll
        for (int k = 0; k < 5; k++) red[wid][k] = s[k];
    }
    __syncthreads();
    if (wid == 0 && lane < 5) {
        float t = 0.f;
#pragma unroll
        for (int w = 0; w < 8; w++) t += red[w][lane];
        atomicAdd(&g_enc_stats[lane], (double)t);
    }
    int off = TB - B;
    for (int i = idx; i < B; i += stride) {
        g_last[2 * i]     = obs[2 * (off + i)]     * invx;
        g_last[2 * i + 1] = obs[2 * (off + i) + 1] * invy;
    }
}

// ---------------- smem layout (shared by k_enc / k_dec) ----------------------
#define O_WH   0
#define O_WL   45056
#define O_AH   90112
#define O_AL   101376
#define O_BIAS 112640
#define O_FOLD 113664
#define LSTM_SMEM 113920

// ======================= fused 8-step encoder ================================
__global__ void __launch_bounds__(512, 1)
k_enc(const float* __restrict__ obs, int B, int nTiles,
      const float* __restrict__ seW1, const float* __restrict__ seb1,
      const float* __restrict__ seg, const float* __restrict__ seb,
      const void* pxm, const void* pym, float Ninv) {
    extern __shared__ char sm[];
    float* bs = (float*)(sm + O_BIAS);
    float* fold = (float*)(sm + O_FOLD);
    u32 smb = smem_u32(sm);
    int tid = threadIdx.x, wid = tid >> 5, lane = tid & 31;

    {   // stage weights
        const float4* s1 = (const float4*)g_Wh;
        const float4* s2 = (const float4*)g_Wl;
        float4* d1 = (float4*)(sm + O_WH);
        float4* d2 = (float4*)(sm + O_WL);
        for (int i = tid; i < 2816; i += 512) { d1[i] = s1[i]; d2[i] = s2[i]; }
    }
    if (tid < 256) bs[tid] = g_bias[tid];
    if (blockIdx.x == 0 && tid < 32) g_hp_stats[tid] = 0.0;
    if (tid < 16) {   // encode BN fold (analytic, from 5 moments)
        const double* st = g_enc_stats;
        double mx = st[0] * Ninv, my = st[1] * Ninv;
        double vxx = st[2] * Ninv - mx * mx;
        double vyy = st[3] * Ninv - my * my;
        double cxy = st[4] * Ninv - mx * my;
        float w0 = seW1[2 * tid], w1 = seW1[2 * tid + 1];
        float mu = (float)(w0 * mx + w1 * my) + seb1[tid];
        float var = (float)((double)w0 * w0 * vxx + (double)w1 * w1 * vyy +
                            2.0 * (double)w0 * w1 * cxy);
        float sc = seg[tid] * rsqrtf(var + EPSBN);
        float ix = 1.f / scalar_f(pxm), iy = 1.f / scalar_f(pym);
        fold[tid]      = w0 * sc * ix;
        fold[16 + tid] = w1 * sc * iy;
        fold[32 + tid] = (seb1[tid] - mu) * sc + seb[tid];
    }
    __syncthreads();

    int wm = wid & 1, wn = wid >> 1;
    int j0 = wn * 8 + (lane & 3) * 2;
    float bj[4][2];
#pragma unroll
    for (int g = 0; g < 4; g++) { bj[g][0] = bs[g * 64 + j0]; bj[g][1] = bs[g * 64 + j0 + 1]; }

    // hoist Bh for kt < 3
    u32 bh[3][4][2];
    {
        u32 nrow = (u32)(wn * 8 + (lane & 7));
        u32 gsel = (u32)(((lane >> 4) & 1) * 64);
        u32 ksel = (u32)(((lane >> 3) & 1) * 16);
#pragma unroll
        for (int kt = 0; kt < 3; kt++) {
#pragma unroll
            for (int p = 0; p < 2; p++) {
                u32 r4[4];
                ldsm4(r4, smb + O_WH +
                      ((u32)(p * 2) * 64 + gsel + nrow) * (WSTR * 2) + ksel + (u32)(kt * 32));
                bh[kt][2 * p][0] = r4[0]; bh[kt][2 * p][1] = r4[1];
                bh[kt][2 * p + 1][0] = r4[2]; bh[kt][2 * p + 1][1] = r4[3];
            }
        }
    }

    u32 aRowOff = (u32)((wm * 32 + (lane & 15)) * (WSTR * 2));
    u32 aColSel = (u32)(((lane >> 4) & 1) * 16);
    u32 bRow = (u32)(wn * 8 + (lane & 7));
    u32 bGsel = (u32)(((lane >> 4) & 1) * 64);
    u32 bKsel = (u32)(((lane >> 3) & 1) * 16);
    int srow = tid >> 3, sseg = tid & 7, j2 = sseg * 2;
    float fa0 = fold[j2], fb0 = fold[16 + j2], fc0 = fold[32 + j2];
    float fa1 = fold[j2 + 1], fb1 = fold[16 + j2 + 1], fc1 = fold[32 + j2 + 1];

    for (int tile = blockIdx.x; tile < nTiles; tile += gridDim.x) {
        int row0 = tile * 64;
        {   // stage feats for t = 0
            float x = obs[2 * (size_t)(row0 + srow)];
            float y = obs[2 * (size_t)(row0 + srow) + 1];
            float f0 = fmaxf(fa0 * x + fb0 * y + fc0, 0.f);
            float f1 = fmaxf(fa1 * x + fb1 * y + fc1, 0.f);
            int off = srow * (WSTR * 2) + j2 * 2;
            *(u32*)(sm + O_AH + off) = pack_bf16_hi(f0, f1);
            *(u32*)(sm + O_AL + off) = pack_bf16_lo(f0, f1);
        }
        float creg[2][2][2];

        for (int t = 0; t < T_OBS; t++) {
            __syncthreads();
            float acc[2][4][4];
#pragma unroll
            for (int mt = 0; mt < 2; mt++)
#pragma unroll
                for (int g = 0; g < 4; g++)
#pragma unroll
                    for (int e = 0; e < 4; e++) acc[mt][g][e] = 0.f;
            int nkt = t ? 5 : 1;
#pragma unroll
            for (int kt = 0; kt < 5; kt++) {
                if (kt >= nkt) break;
                u32 kOff = (u32)(kt * 32);
                u32 ah0[4], ah1[4], al0[4], al1[4];
                u32 aAddr = smb + O_AH + aRowOff + aColSel + kOff;
                ldsm4(ah0, aAddr);
                ldsm4(ah1, aAddr + 16 * (WSTR * 2));
                u32 aAddrL = smb + O_AL + aRowOff + aColSel + kOff;
                ldsm4(al0, aAddrL);
                ldsm4(al1, aAddrL + 16 * (WSTR * 2));
                u32 bl[4][2];
#pragma unroll
                for (int p = 0; p < 2; p++) {
                    u32 r4[4];
                    ldsm4(r4, smb + O_WL +
                          ((u32)(p * 2) * 64 + bGsel + bRow) * (WSTR * 2) + bKsel + kOff);
                    bl[2 * p][0] = r4[0]; bl[2 * p][1] = r4[1];
                    bl[2 * p + 1][0] = r4[2]; bl[2 * p + 1][1] = r4[3];
                }
                if (kt < 3) {
#pragma unroll
                    for (int g = 0; g < 4; g++) {
                        mma16816(acc[0][g], ah0, bh[kt][g]);
                        mma16816(acc[1][g], ah1, bh[kt][g]);
                        mma16816(acc[0][g], al0, bh[kt][g]);
                        mma16816(acc[1][g], al1, bh[kt][g]);
                        mma16816(acc[0][g], ah0, bl[g]);
                        mma16816(acc[1][g], ah1, bl[g]);
                    }
                } else {
                    u32 bhd[4][2];
#pragma unroll
                    for (int p = 0; p < 2; p++) {
                        u32 r4[4];
                        ldsm4(r4, smb + O_WH +
                              ((u32)(p * 2) * 64 + bGsel + bRow) * (WSTR * 2) + bKsel + kOff);
                        bhd[2 * p][0] = r4[0]; bhd[2 * p][1] = r4[1];
                        bhd[2 * p + 1][0] = r4[2]; bhd[2 * p + 1][1] = r4[3];
                    }
#pragma unroll
                    for (int g = 0; g < 4; g++) {
                        mma16816(acc[0][g], ah0, bhd[g]);
                        mma16816(acc[1][g], ah1, bhd[g]);
                        mma16816(acc[0][g], al0, bhd[g]);
                        mma16816(acc[1][g], al1, bhd[g]);
                        mma16816(acc[0][g], ah0, bl[g]);
                        mma16816(acc[1][g], ah1, bl[g]);
                    }
                }
            }

            // pointwise (c in registers)
            float hn[2][2][2];
#pragma unroll
            for (int mt = 0; mt < 2; mt++)
#pragma unroll
                for (int rr = 0; rr < 2; rr++)
#pragma unroll
                    for (int cc = 0; cc < 2; cc++) {
                        int e = rr * 2 + cc;
                        float iv = acc[mt][0][e] + bj[0][cc];
                        float fv = acc[mt][1][e] + bj[1][cc];
                        float gv = acc[mt][2][e] + bj[2][cc];
                        float ov = acc[mt][3][e] + bj[3][cc];
                        float cold = t ? creg[mt][rr][cc] : 0.f;
                        float cnew = fast_sig(fv) * cold + fast_sig(iv) * fast_tanh(gv);
                        creg[mt][rr][cc] = cnew;
                        hn[mt][rr][cc] = fast_sig(ov) * fast_tanh(cnew);
                    }
            __syncthreads();   // all A reads done

            if (t == T_OBS - 1) {
#pragma unroll
                for (int mt = 0; mt < 2; mt++)
#pragma unroll
                    for (int rr = 0; rr < 2; rr++) {
                        int r = row0 + wm * 32 + mt * 16 + rr * 8 + (lane >> 2);
                        *(float2*)(g_h + (size_t)r * 64 + j0) =
                            make_float2(hn[mt][rr][0], hn[mt][rr][1]);
                        *(float2*)(g_c + (size_t)r * 64 + j0) =
                            make_float2(creg[mt][rr][0], creg[mt][rr][1]);
                    }
            } else {
                // write h into A buffer (bf16 hi/lo) for next step
#pragma unroll
                for (int mt = 0; mt < 2; mt++)
#pragma unroll
                    for (int rr = 0; rr < 2; rr++) {
                        int lrow = wm * 32 + mt * 16 + rr * 8 + (lane >> 2);
                        int off = lrow * (WSTR * 2) + (16 + j0) * 2;
                        *(u32*)(sm + O_AH + off) = pack_bf16_hi(hn[mt][rr][0], hn[mt][rr][1]);
                        *(u32*)(sm + O_AL + off) = pack_bf16_lo(hn[mt][rr][0], hn[mt][rr][1]);
                    }
                // stage feats for t+1
                const float* xyt = obs + (size_t)(t + 1) * B * 2;
                float x = xyt[2 * (size_t)(row0 + srow)];
                float y = xyt[2 * (size_t)(row0 + srow) + 1];
                float f0 = fmaxf(fa0 * x + fb0 * y + fc0, 0.f);
                float f1 = fmaxf(fa1 * x + fb1 * y + fc1, 0.f);
                int off = srow * (WSTR * 2) + j2 * 2;
                *(u32*)(sm + O_AH + off) = pack_bf16_hi(f0, f1);
                *(u32*)(sm + O_AL + off) = pack_bf16_lo(f0, f1);
            }
        }
    }
}

// ======================= decode LSTM step ====================================
__global__ void __launch_bounds__(512, 1)
k_dec(int B, int nTiles,
      const float* __restrict__ seW1, const float* __restrict__ seb1,
      const float* __restrict__ seg, const float* __restrict__ seb, float Ninv) {
    extern __shared__ char sm[];
    float* bs = (float*)(sm + O_BIAS);
    float* fold = (float*)(sm + O_FOLD);
    u32 smb = smem_u32(sm);
    int tid = threadIdx.x, wid = tid >> 5, lane = tid & 31;

    {
        const float4* s1 = (const float4*)g_Wh;
        const float4* s2 = (const float4*)g_Wl;
        float4* d1 = (float4*)(sm + O_WH);
        float4* d2 = (float4*)(sm + O_WL);
        for (int i = tid; i < 2816; i += 512) { d1[i] = s1[i]; d2[i] = s2[i]; }
    }
    if (tid < 256) bs[tid] = g_bias[tid];
    if (blockIdx.x == 0 && tid < 32) g_hp_stats[tid] = 0.0;
    if (tid < 16) {   // decode BN fold from se stats (inputs already in [0,1])
        const double* st = g_se_stats;
        double mx = st[0] * Ninv, my = st[1] * Ninv;
        double vxx = st[2] * Ninv - mx * mx;
        double vyy = st[3] * Ninv - my * my;
        double cxy = st[4] * Ninv - mx * my;
        float w0 = seW1[2 * tid], w1 = seW1[2 * tid + 1];
        float mu = (float)(w0 * mx + w1 * my) + seb1[tid];
        float var = (float)((double)w0 * w0 * vxx + (double)w1 * w1 * vyy +
                            2.0 * (double)w0 * w1 * cxy);
        float sc = seg[tid] * rsqrtf(var + EPSBN);
        fold[tid]      = w0 * sc;
        fold[16 + tid] = w1 * sc;
        fold[32 + tid] = (seb1[tid] - mu) * sc + seb[tid];
    }
    __syncthreads();

    int wm = wid & 1, wn = wid >> 1;
    int j0 = wn * 8 + (lane & 3) * 2;
    float bj[4][2];
#pragma unroll
    for (int g = 0; g < 4; g++) { bj[g][0] = bs[g * 64 + j0]; bj[g][1] = bs[g * 64 + j0 + 1]; }

    u32 bh[5][4][2];
    {
        u32 nrow = (u32)(wn * 8 + (lane & 7));
        u32 gsel = (u32)(((lane >> 4) & 1) * 64);
        u32 ksel = (u32)(((lane >> 3) & 1) * 16);
#pragma unroll
        for (int kt = 0; kt < 5; kt++) {
#pragma unroll
            for (int p = 0; p < 2; p++) {
                u32 r4[4];
                ldsm4(r4, smb + O_WH +
                      ((u32)(p * 2) * 64 + gsel + nrow) * (WSTR * 2) + ksel + (u32)(kt * 32));
                bh[kt][2 * p][0] = r4[0]; bh[kt][2 * p][1] = r4[1];
                bh[kt][2 * p + 1][0] = r4[2]; bh[kt][2 * p + 1][1] = r4[3];
            }
        }
    }

    u32 aRowOff = (u32)((wm * 32 + (lane & 15)) * (WSTR * 2));
    u32 aColSel = (u32)(((lane >> 4) & 1) * 16);
    u32 bRow = (u32)(wn * 8 + (lane & 7));
    u32 bGsel = (u32)(((lane >> 4) & 1) * 64);
    u32 bKsel = (u32)(((lane >> 3) & 1) * 16);
    int srow = tid >> 3, sseg = tid & 7, j2 = sseg * 2;
    float fa0 = fold[j2], fb0 = fold[16 + j2], fc0 = fold[32 + j2];
    float fa1 = fold[j2 + 1], fb1 = fold[16 + j2 + 1], fc1 = fold[32 + j2 + 1];

    for (int tile = blockIdx.x; tile < nTiles; tile += gridDim.x) {
        int row0 = tile * 64;
        int r = row0 + srow;
        {   // coalesced h staging: 8 threads per row, LDG.128 x2 -> STS.128 hi/lo
            const float4* hp = (const float4*)(g_h + (size_t)r * 64 + sseg * 8);
            float4 h0 = hp[0], h1 = hp[1];
            uint4 hi, lo;
            hi.x = pack_bf16_hi(h0.x, h0.y); lo.x = pack_bf16_lo(h0.x, h0.y);
            hi.y = pack_bf16_hi(h0.z, h0.w); lo.y = pack_bf16_lo(h0.z, h0.w);
            hi.z = pack_bf16_hi(h1.x, h1.y); lo.z = pack_bf16_lo(h1.x, h1.y);
            hi.w = pack_bf16_hi(h1.z, h1.w); lo.w = pack_bf16_lo(h1.z, h1.w);
            int off = srow * (WSTR * 2) + 32 + sseg * 16;
            *(uint4*)(sm + O_AH + off) = hi;
            *(uint4*)(sm + O_AL + off) = lo;
            // feats from last_pos
            float x = g_last[2 * (size_t)r], y = g_last[2 * (size_t)r + 1];
            float f0 = fmaxf(fa0 * x + fb0 * y + fc0, 0.f);
            float f1 = fmaxf(fa1 * x + fb1 * y + fc1, 0.f);
            int offf = srow * (WSTR * 2) + j2 * 2;
            *(u32*)(sm + O_AH + offf) = pack_bf16_hi(f0, f1);
            *(u32*)(sm + O_AL + offf) = pack_bf16_lo(f0, f1);
        }
        __syncthreads();

        float acc[2][4][4];
#pragma unroll
        for (int mt = 0; mt < 2; mt++)
#pragma unroll
            for (int g = 0; g < 4; g++)
#pragma unroll
                for (int e = 0; e < 4; e++) acc[mt][g][e] = 0.f;

#pragma unroll
        for (int kt = 0; kt < 5; kt++) {
            u32 kOff = (u32)(kt * 32);
            u32 ah0[4], ah1[4], al0[4], al1[4];
            u32 aAddr = smb + O_AH + aRowOff + aColSel + kOff;
            ldsm4(ah0, aAddr);
            ldsm4(ah1, aAddr + 16 * (WSTR * 2));
            u32 aAddrL = smb + O_AL + aRowOff + aColSel + kOff;
            ldsm4(al0, aAddrL);
            ldsm4(al1, aAddrL + 16 * (WSTR * 2));
            u32 bl[4][2];
#pragma unroll
            for (int p = 0; p < 2; p++) {
                u32 r4[4];
                ldsm4(r4, smb + O_WL +
                      ((u32)(p * 2) * 64 + bGsel + bRow) * (WSTR * 2) + bKsel + kOff);
                bl[2 * p][0] = r4[0]; bl[2 * p][1] = r4[1];
                bl[2 * p + 1][0] = r4[2]; bl[2 * p + 1][1] = r4[3];
            }
#pragma unroll
            for (int g = 0; g < 4; g++) {
                mma16816(acc[0][g], ah0, bh[kt][g]);
                mma16816(acc[1][g], ah1, bh[kt][g]);
                mma16816(acc[0][g], al0, bh[kt][g]);
                mma16816(acc[1][g], al1, bh[kt][g]);
                mma16816(acc[0][g], ah0, bl[g]);
                mma16816(acc[1][g], ah1, bl[g]);
            }
        }

#pragma unroll
        for (int mt = 0; mt < 2; mt++)
#pragma unroll
            for (int rr = 0; rr < 2; rr++) {
                int rw = row0 + wm * 32 + mt * 16 + rr * 8 + (lane >> 2);
                float2 c2 = *(float2*)(g_c + (size_t)rw * 64 + j0);
                float cn[2], hn[2];
#pragma unroll
                for (int cc = 0; cc < 2; cc++) {
                    int e = rr * 2 + cc;
                    float iv = acc[mt][0][e] + bj[0][cc];
                    float fv = acc[mt][1][e] + bj[1][cc];
                    float gv = acc[mt][2][e] + bj[2][cc];
                    float ov = acc[mt][3][e] + bj[3][cc];
                    float cold = cc ? c2.y : c2.x;
                    float cnew = fast_sig(fv) * cold + fast_sig(iv) * fast_tanh(gv);
                    cn[cc] = cnew;
                    hn[cc] = fast_sig(ov) * fast_tanh(cnew);
                }
                *(float2*)(g_c + (size_t)rw * 64 + j0) = make_float2(cn[0], cn[1]);
                *(float2*)(g_h + (size_t)rw * 64 + j0) = make_float2(hn[0], hn[1]);
            }
        __syncthreads();
    }
}

// ---------------- hidden2pos proj + stats (also zeroes se stats) ------------
__global__ void k_hp(const float* __restrict__ hpW1, const float* __restrict__ hpb1, int B) {
    __shared__ float Ws[1024];
    __shared__ float red[8][32];
    for (int i = threadIdx.x; i < 1024; i += 256) Ws[i] = hpW1[i];
    if (blockIdx.x == 0 && threadIdx.x < 5) g_se_stats[threadIdx.x] = 0.0;
    __syncthreads();
    int r0 = (blockIdx.x * 256 + threadIdx.x) * 2;
    float z0[16], z1[16];
#pragma unroll
    for (int jj = 0; jj < 16; jj++) { float b = hpb1[jj]; z0[jj] = b; z1[jj] = b; }
    const float4* ha = (const float4*)(g_h + (size_t)r0 * 64);
    const float4* hb = (const float4*)(g_h + (size_t)(r0 + 1) * 64);
#pragma unroll 4
    for (int kk = 0; kk < 16; kk++) {
        float4 a = ha[kk], b = hb[kk];
#pragma unroll
        for (int jj = 0; jj < 16; jj++) {
            const float* w = &Ws[jj * 64 + 4 * kk];
            z0[jj] += a.x * w[0] + a.y * w[1] + a.z * w[2] + a.w * w[3];
            z1[jj] += b.x * w[0] + b.y * w[1] + b.z * w[2] + b.w * w[3];
        }
    }
    float4* zo = (float4*)(g_z + (size_t)r0 * 16);
    zo[0] = make_float4(z0[0], z0[1], z0[2], z0[3]);
    zo[1] = make_float4(z0[4], z0[5], z0[6], z0[7]);
    zo[2] = make_float4(z0[8], z0[9], z0[10], z0[11]);
    zo[3] = make_float4(z0[12], z0[13], z0[14], z0[15]);
    zo[4] = make_float4(z1[0], z1[1], z1[2], z1[3]);
    zo[5] = make_float4(z1[4], z1[5], z1[6], z1[7]);
    zo[6] = make_float4(z1[8], z1[9], z1[10], z1[11]);
    zo[7] = make_float4(z1[12], z1[13], z1[14], z1[15]);
    float sv[16], qv[16];
#pragma unroll
    for (int jj = 0; jj < 16; jj++) {
        sv[jj] = z0[jj] + z1[jj];
        qv[jj] = z0[jj] * z0[jj] + z1[jj] * z1[jj];
    }
    int wid = threadIdx.x >> 5, lane = threadIdx.x & 31;
#pragma unroll
    for (int jj = 0; jj < 16; jj++) { sv[jj] = wred(sv[jj]); qv[jj] = wred(qv[jj]); }
    if (lane == 0) {
#pragma unroll
        for (int jj = 0; jj < 16; jj++) { red[wid][jj] = sv[jj]; red[wid][16 + jj] = qv[jj]; }
    }
    __syncthreads();
    if (wid == 0) {
        float t = 0.f;
#pragma unroll
        for (int w = 0; w < 8; w++) t += red[w][lane];
        atomicAdd(&g_hp_stats[lane], (double)t);
    }
}

// ---------------- positions: BN(inline)+relu+W2, sigmoid, out, se moments ---
__global__ void k_pos(const float* __restrict__ hpW2, const float* __restrict__ hpb2,
                      const float* __restrict__ gamma, const float* __restrict__ beta,
                      float* __restrict__ out, const void* pxm, const void* pym,
                      float Binv, int B) {
    __shared__ float sc[16], sh[16];
    __shared__ float red[8][5];
    if (threadIdx.x < 16) {
        int j = threadIdx.x;
        double mu = g_hp_stats[j] * Binv;
        double var = g_hp_stats[16 + j] * Binv - mu * mu;
        float s = gamma[j] * rsqrtf((float)var + EPSBN);
        sc[j] = s;
        sh[j] = beta[j] - (float)mu * s;
    }
    __syncthreads();
    int row = blockIdx.x * 256 + threadIdx.x;
    const float4* zr = (const float4*)(g_z + (size_t)row * 16);
    float px = hpb2[0], py = hpb2[1];
#pragma unroll
    for (int q4 = 0; q4 < 4; q4++) {
        float4 v = zr[q4];
        float vv[4] = {v.x, v.y, v.z, v.w};
#pragma unroll
        for (int e = 0; e < 4; e++) {
            int j = q4 * 4 + e;
            float t = fmaxf(vv[e] * sc[j] + sh[j], 0.f);
            px += t * hpW2[j];
            py += t * hpW2[16 + j];
        }
    }
    float lx = fast_sig(px + g_last[2 * row]);
    float ly = fast_sig(py + g_last[2 * row + 1]);
    g_last[2 * row] = lx;
    g_last[2 * row + 1] = ly;
    out[2 * row]     = lx * scalar_f(pxm);
    out[2 * row + 1] = ly * scalar_f(pym);
    float s[5] = {lx, ly, lx * lx, ly * ly, lx * ly};
    int wid = threadIdx.x >> 5, lane = threadIdx.x & 31;
#pragma unroll
    for (int k = 0; k < 5; k++) s[k] = wred(s[k]);
    if (lane == 0) {
#pragma unroll
        for (int k = 0; k < 5; k++) red[wid][k] = s[k];
    }
    __syncthreads();
    if (wid == 0 && lane < 5) {
        float t = 0.f;
#pragma unroll
        for (int w = 0; w < 8; w++) t += red[w][lane];
        atomicAdd(&g_se_stats[lane], (double)t);
    }
}

// ---------------- launch ------------------------------------------------------
extern "C" void kernel_launch(void* const* d_in, const int* in_sizes, int n_in,
                              void* d_out, int out_size) {
    const float* obs  = (const float*)d_in[0];
    const float* seW1 = (const float*)d_in[1];
    const float* seb1 = (const float*)d_in[2];
    const float* seg  = (const float*)d_in[3];
    const float* seb  = (const float*)d_in[4];
    const float* seW2 = (const float*)d_in[5];
    const float* seb2 = (const float*)d_in[6];
    const float* hpW1 = (const float*)d_in[7];
    const float* hpb1 = (const float*)d_in[8];
    const float* hpg  = (const float*)d_in[9];
    const float* hpb  = (const float*)d_in[10];
    const float* hpW2 = (const float*)d_in[11];
    const float* hpb2 = (const float*)d_in[12];
    const float* Wih  = (const float*)d_in[13];
    const float* Whh  = (const float*)d_in[14];
    const float* bih  = (const float*)d_in[15];
    const float* bhh  = (const float*)d_in[16];
    const void*  pxm  = d_in[17];
    const void*  pym  = d_in[18];

    int B = in_sizes[0] / (T_OBS * 2);
    int TB = T_OBS * B;
    int predLen = out_size / (2 * B);
    float* out = (float*)d_out;
    int nTiles = B / 64;

    cudaFuncSetAttribute(k_enc, cudaFuncAttributeMaxDynamicSharedMemorySize, LSTM_SMEM);
    cudaFuncSetAttribute(k_dec, cudaFuncAttributeMaxDynamicSharedMemorySize, LSTM_SMEM);

    k_prep<<<1, 256>>>(Wih, Whh, bih, bhh, seW2, seb2);
    k_moments<<<512, 256>>>(obs, pxm, pym, TB, B);
    k_enc<<<148, 512, LSTM_SMEM>>>(obs, B, nTiles, seW1, seb1, seg, seb,
                                   pxm, pym, 1.0f / (float)TB);

    for (int s = 0; s < predLen; s++) {
        k_hp<<<B / 512, 256>>>(hpW1, hpb1, B);
        k_pos<<<B / 256, 256>>>(hpW2, hpb2, hpg, hpb, out + (size_t)s * B * 2,
                                pxm, pym, 1.0f / (float)B, B);
        if (s + 1 < predLen)
            k_dec<<<148, 512, LSTM_SMEM>>>(B, nTiles, seW1, seb1, seg, seb,
                                           1.0f / (float)B);
    }
}